// round 10
// baseline (speedup 1.0000x reference)
#include <cuda_runtime.h>

#define NNODES 100000
#define NEDGES 1600000
#define NREL 4
#define NKEYS (NREL * NNODES)   // composite key = dst*4 + rel

// Scratch (allocation-free). No S buffers anymore — means live in smem.
__device__ __align__(16) float g_h1[NNODES * 16];
__device__ __align__(16) float g_h2[NNODES * 32];
__device__ int g_bins[NKEYS];       // histogram
__device__ int g_off[NKEYS + 1];    // exclusive offsets (CSR)
__device__ int g_fill[NKEYS];       // fill cursors
__device__ int g_bsum[1024];        // scan block sums
__device__ int g_ssrc[NEDGES];      // src ids sorted by key (dst*4+rel)

typedef unsigned long long ull;

__device__ __forceinline__ void ffma2(ull& acc, ull a, ull b) {
    asm("fma.rn.f32x2 %0, %1, %2, %0;" : "+l"(acc) : "l"(a), "l"(b));
}
__device__ __forceinline__ ull bcast2(float v) {
    ull r;
    unsigned int u = __float_as_uint(v);
    asm("mov.b64 %0, {%1, %1};" : "=l"(r) : "r"(u));
    return r;
}

// ---------------------------------------------------------------------------
// CSR build: histogram -> exclusive scan -> fill (identical to R9, passing)
// ---------------------------------------------------------------------------
__global__ void hist_kernel(const int* __restrict__ dst,
                            const int* __restrict__ et,
                            int* __restrict__ bins, int e) {
    int i = blockIdx.x * blockDim.x + threadIdx.x;
    if (i < e) atomicAdd(&bins[dst[i] * 4 + et[i]], 1);
}

__global__ void scan1_kernel(const int* __restrict__ bins,
                             int* __restrict__ off,
                             int* __restrict__ bsum, int nk) {
    __shared__ int sh[512];
    int t = threadIdx.x;
    int g = blockIdx.x * 512 + t;
    int v = (g < nk) ? bins[g] : 0;
    sh[t] = v;
    __syncthreads();
    for (int s = 1; s < 512; s <<= 1) {
        int add = (t >= s) ? sh[t - s] : 0;
        __syncthreads();
        sh[t] += add;
        __syncthreads();
    }
    if (g < nk) off[g] = sh[t] - v;
    if (t == 511) bsum[blockIdx.x] = sh[511];
}

__global__ void scan2_kernel(int* __restrict__ bsum, int nb) {
    __shared__ int sh[1024];
    int t = threadIdx.x;
    int v = (t < nb) ? bsum[t] : 0;
    sh[t] = v;
    __syncthreads();
    for (int s = 1; s < 1024; s <<= 1) {
        int add = (t >= s) ? sh[t - s] : 0;
        __syncthreads();
        sh[t] += add;
        __syncthreads();
    }
    if (t < nb) bsum[t] = sh[t] - v;
}

__global__ void scan3_kernel(int* __restrict__ off,
                             const int* __restrict__ bsum, int nk, int e) {
    int g = blockIdx.x * 512 + threadIdx.x;
    if (g < nk) off[g] += bsum[g >> 9];
    if (g == nk) off[g] = e;
}

__global__ void fill_kernel(const int* __restrict__ src,
                            const int* __restrict__ dst,
                            const int* __restrict__ et,
                            const int* __restrict__ off,
                            int* __restrict__ fill,
                            int* __restrict__ ssrc, int e) {
    int i = blockIdx.x * blockDim.x + threadIdx.x;
    if (i >= e) return;
    int key = dst[i] * 4 + et[i];
    int pos = off[key] + atomicAdd(&fill[key], 1);
    ssrc[pos] = src[i];
}

// ---------------------------------------------------------------------------
// FUSED layer kernel: gather (CSR means, in registers -> smem) + combine
// (smem tile @ smem weights -> out). No global S round-trip at all.
//
// Gather: warp per node; lane = (g, c): C4 lanes cover the float4 row, G
// edge-groups in flight. Butterfly-reduce across g, scale by 1/cnt, write
// smem row [x | m0 | m1 | m2 | m3] (padded stride).
// Combine: SPLIT threads/node x COLS=8 columns, NT nodes/thread, f32x2.
// Persistent grid-stride over tiles; weights staged once per block.
// ---------------------------------------------------------------------------
template <int DIN, int DOUT, int SPLIT, int NT, bool RELU>
__global__ void __launch_bounds__(256)
fused_kernel(const float* __restrict__ h,     // [n, DIN] layer input
             const int* __restrict__ off,     // [4n+1]
             const int* __restrict__ ssrc,    // [E]
             const float* __restrict__ W,     // [R, DIN, DOUT]
             const float* __restrict__ root,  // [DIN, DOUT]
             const float* __restrict__ bias,  // [DOUT]
             float* __restrict__ out, int n, int tiles) {
    constexpr int COLS = 8;
    constexpr int NG   = 256 / SPLIT;
    constexpr int NPB  = NG * NT;        // nodes per tile
    constexpr int T    = NPB / 8;        // gather rounds per warp (8 warps)
    constexpr int C4   = DIN / 4;        // float4 lanes per row
    constexpr int G    = 32 / C4;        // edge groups in flight
    constexpr int CH   = DIN / 4;
    constexpr int ROW  = 5 * DIN;
    constexpr int ROWP = ROW + 4;
    constexpr int WSZ  = 5 * DIN * DOUT;

    extern __shared__ float smem[];
    float* swt = smem;                    // weights [5*DIN*DOUT]
    float* sin = smem + WSZ;              // tile [NPB][ROWP]

    const int tid = threadIdx.x;
    {   // stage weights once per block
        const float4* r4 = reinterpret_cast<const float4*>(root);
        const float4* w4 = reinterpret_cast<const float4*>(W);
        float4* d4 = reinterpret_cast<float4*>(swt);
        for (int i = tid; i < DIN * DOUT / 4; i += 256) d4[i] = __ldg(r4 + i);
        for (int i = tid; i < NREL * DIN * DOUT / 4; i += 256)
            d4[DIN * DOUT / 4 + i] = __ldg(w4 + i);
    }

    const int wid  = tid >> 5;
    const int lane = tid & 31;
    const int c    = lane & (C4 - 1);
    const int g    = lane / C4;
    const float4* h4 = reinterpret_cast<const float4*>(h);

    const int ng = tid / SPLIT;
    const int sp = tid % SPLIT;
    const float* wbase = swt + sp * COLS;
    const ull* bb = reinterpret_cast<const ull*>(bias + sp * COLS);

    for (int tile = blockIdx.x; tile < tiles; tile += gridDim.x) {
        const int tstart = tile * NPB;
        __syncthreads();   // prev combine done reading sin

        // ---- gather phase: 8 warps fill NPB smem rows ----
        for (int t = 0; t < T; t++) {
            const int local = wid + (t << 3);
            const int node = tstart + local;
            if (node >= n) continue;   // warp-uniform
            const int ob = 4 * node;
            const int o0 = __ldg(off + ob);
            const int o1 = __ldg(off + ob + 1);
            const int o2 = __ldg(off + ob + 2);
            const int o3 = __ldg(off + ob + 3);
            const int o4 = __ldg(off + ob + 4);
            const int deg = o4 - o0, d1 = o1 - o0, d2 = o2 - o0, d3 = o3 - o0;

            float4 a0 = {0.f,0.f,0.f,0.f}, a1 = a0, a2 = a0, a3 = a0;
            int i = g;
            int s_cur = (i < deg) ? __ldg(ssrc + o0 + i) : 0;
            while (i < deg) {
                const int inx = i + G;
                const int s_nxt = (inx < deg) ? __ldg(ssrc + o0 + inx) : 0;
                const float4 f = __ldg(h4 + (size_t)s_cur * C4 + c);
                if (i < d1)      { a0.x+=f.x; a0.y+=f.y; a0.z+=f.z; a0.w+=f.w; }
                else if (i < d2) { a1.x+=f.x; a1.y+=f.y; a1.z+=f.z; a1.w+=f.w; }
                else if (i < d3) { a2.x+=f.x; a2.y+=f.y; a2.z+=f.z; a2.w+=f.w; }
                else             { a3.x+=f.x; a3.y+=f.y; a3.z+=f.z; a3.w+=f.w; }
                i = inx;
                s_cur = s_nxt;
            }
            // butterfly across the G edge groups
#pragma unroll
            for (int m = C4; m < 32; m <<= 1) {
                a0.x += __shfl_xor_sync(~0u, a0.x, m);
                a0.y += __shfl_xor_sync(~0u, a0.y, m);
                a0.z += __shfl_xor_sync(~0u, a0.z, m);
                a0.w += __shfl_xor_sync(~0u, a0.w, m);
                a1.x += __shfl_xor_sync(~0u, a1.x, m);
                a1.y += __shfl_xor_sync(~0u, a1.y, m);
                a1.z += __shfl_xor_sync(~0u, a1.z, m);
                a1.w += __shfl_xor_sync(~0u, a1.w, m);
                a2.x += __shfl_xor_sync(~0u, a2.x, m);
                a2.y += __shfl_xor_sync(~0u, a2.y, m);
                a2.z += __shfl_xor_sync(~0u, a2.z, m);
                a2.w += __shfl_xor_sync(~0u, a2.w, m);
                a3.x += __shfl_xor_sync(~0u, a3.x, m);
                a3.y += __shfl_xor_sync(~0u, a3.y, m);
                a3.z += __shfl_xor_sync(~0u, a3.z, m);
                a3.w += __shfl_xor_sync(~0u, a3.w, m);
            }
            float* row = sin + local * ROWP;
            if (g == 0) {
                const float i0 = 1.0f / (float)max(d1, 1);
                const float i1 = 1.0f / (float)max(d2 - d1, 1);
                const float i2 = 1.0f / (float)max(d3 - d2, 1);
                const float i3 = 1.0f / (float)max(deg - d3, 1);
                float4 m0 = {a0.x*i0, a0.y*i0, a0.z*i0, a0.w*i0};
                float4 m1 = {a1.x*i1, a1.y*i1, a1.z*i1, a1.w*i1};
                float4 m2 = {a2.x*i2, a2.y*i2, a2.z*i2, a2.w*i2};
                float4 m3 = {a3.x*i3, a3.y*i3, a3.z*i3, a3.w*i3};
                *reinterpret_cast<float4*>(row + 1*DIN + 4*c) = m0;
                *reinterpret_cast<float4*>(row + 2*DIN + 4*c) = m1;
                *reinterpret_cast<float4*>(row + 3*DIN + 4*c) = m2;
                *reinterpret_cast<float4*>(row + 4*DIN + 4*c) = m3;
            } else if (g == 1) {
                *reinterpret_cast<float4*>(row + 4*c) =
                    __ldg(h4 + (size_t)node * C4 + c);
            }
        }
        __syncthreads();

        // ---- combine phase: out = bias + [x|m] @ [root|W] from smem ----
        ull acc[NT][4];
#pragma unroll
        for (int i = 0; i < NT; i++)
#pragma unroll
            for (int j = 0; j < 4; j++) acc[i][j] = bb[j];

        const float* in0 = sin + ng * ROWP;
#pragma unroll
        for (int rb = 0; rb < 5; rb++) {
#pragma unroll
            for (int c4 = 0; c4 < CH; c4++) {
                ulonglong2 w[4][2];
#pragma unroll
                for (int k = 0; k < 4; k++) {
                    const ulonglong2* wp = reinterpret_cast<const ulonglong2*>(
                        wbase + (rb * DIN + c4 * 4 + k) * DOUT);
                    w[k][0] = wp[0];
                    w[k][1] = wp[1];
                }
#pragma unroll
                for (int i = 0; i < NT; i++) {
                    const float4 v = *reinterpret_cast<const float4*>(
                        in0 + i * NG * ROWP + rb * DIN + c4 * 4);
                    const float vv[4] = {v.x, v.y, v.z, v.w};
#pragma unroll
                    for (int k = 0; k < 4; k++) {
                        const ull v2 = bcast2(vv[k]);
                        ffma2(acc[i][0], v2, w[k][0].x);
                        ffma2(acc[i][1], v2, w[k][0].y);
                        ffma2(acc[i][2], v2, w[k][1].x);
                        ffma2(acc[i][3], v2, w[k][1].y);
                    }
                }
            }
        }

#pragma unroll
        for (int i = 0; i < NT; i++) {
            const int nd = tstart + ng + i * NG;
            if (nd >= n) continue;
            float* op = out + (size_t)nd * DOUT + sp * COLS;
#pragma unroll
            for (int j = 0; j < 4; j++) {
                float2 f = *reinterpret_cast<float2*>(&acc[i][j]);
                if (RELU) {
                    f.x = fmaxf(f.x, 0.0f);
                    f.y = fmaxf(f.y, 0.0f);
                }
                reinterpret_cast<float2*>(op)[j] = f;
            }
        }
    }
}

// ---------------------------------------------------------------------------
// Launcher: CSR build once -> 3 fused layer kernels
// ---------------------------------------------------------------------------
extern "C" void kernel_launch(void* const* d_in, const int* in_sizes, int n_in,
                              void* d_out, int out_size) {
    const float* x     = (const float*)d_in[0];
    const int*   ei    = (const int*)d_in[1];   // [2, E]: src then dst
    const int*   et    = (const int*)d_in[2];
    const float* W1    = (const float*)d_in[3];
    const float* root1 = (const float*)d_in[4];
    const float* b1    = (const float*)d_in[5];
    const float* W2    = (const float*)d_in[6];
    const float* root2 = (const float*)d_in[7];
    const float* b2    = (const float*)d_in[8];
    const float* W3    = (const float*)d_in[9];
    const float* root3 = (const float*)d_in[10];
    const float* b3    = (const float*)d_in[11];
    float* out = (float*)d_out;

    const int n = in_sizes[0] / 16;
    const int e = in_sizes[2];
    const int nk = 4 * n;
    const int* src = ei;
    const int* dst = ei + e;

    float *ph1, *ph2;
    int *pbins, *poff, *pfill, *pbsum, *pssrc;
    cudaGetSymbolAddress((void**)&ph1, g_h1);
    cudaGetSymbolAddress((void**)&ph2, g_h2);
    cudaGetSymbolAddress((void**)&pbins, g_bins);
    cudaGetSymbolAddress((void**)&poff, g_off);
    cudaGetSymbolAddress((void**)&pfill, g_fill);
    cudaGetSymbolAddress((void**)&pbsum, g_bsum);
    cudaGetSymbolAddress((void**)&pssrc, g_ssrc);

    cudaMemsetAsync(pbins, 0, sizeof(int) * nk);
    cudaMemsetAsync(pfill, 0, sizeof(int) * nk);

    const int TB = 256;
    const int NB = (nk + 511) / 512;

    hist_kernel<<<(e + TB - 1) / TB, TB>>>(dst, et, pbins, e);
    scan1_kernel<<<NB, 512>>>(pbins, poff, pbsum, nk);
    scan2_kernel<<<1, 1024>>>(pbsum, NB);
    scan3_kernel<<<(nk + 512) / 512, 512>>>(poff, pbsum, nk, e);
    fill_kernel<<<(e + TB - 1) / TB, TB>>>(src, dst, et, poff, pfill, pssrc, e);

    // smem: weights + NPB*(5*DIN+4) floats
    const int smem1 = (5*16*16 + 128*(5*16+4)) * 4;   // 48128
    const int smem2 = (5*16*32 + 128*(5*16+4)) * 4;   // 53248
    const int smem3 = (5*32*64 + 64*(5*32+4)) * 4;    // 82944

    static bool attr_done = false;
    if (!attr_done) {
        cudaFuncSetAttribute(fused_kernel<16, 16, 2, 1, true>,
                             cudaFuncAttributeMaxDynamicSharedMemorySize, smem1);
        cudaFuncSetAttribute(fused_kernel<16, 32, 4, 2, true>,
                             cudaFuncAttributeMaxDynamicSharedMemorySize, smem2);
        cudaFuncSetAttribute(fused_kernel<32, 64, 8, 2, false>,
                             cudaFuncAttributeMaxDynamicSharedMemorySize, smem3);
        attr_done = true;
    }

    // Layer 1: 16 -> 16, relu. NPB=128
    {
        int tiles = (n + 127) / 128;
        int grid = tiles < 444 ? tiles : 444;
        fused_kernel<16, 16, 2, 1, true><<<grid, 256, smem1>>>(
            x, poff, pssrc, W1, root1, b1, ph1, n, tiles);
    }
    // Layer 2: 16 -> 32, relu. NPB=128
    {
        int tiles = (n + 127) / 128;
        int grid = tiles < 444 ? tiles : 444;
        fused_kernel<16, 32, 4, 2, true><<<grid, 256, smem2>>>(
            ph1, poff, pssrc, W2, root2, b2, ph2, n, tiles);
    }
    // Layer 3: 32 -> 64, no relu. NPB=64
    {
        int tiles = (n + 63) / 64;
        int grid = tiles < 296 ? tiles : 296;
        fused_kernel<32, 64, 8, 2, false><<<grid, 256, smem3>>>(
            ph2, poff, pssrc, W3, root3, b3, out, n, tiles);
    }
}